// round 16
// baseline (speedup 1.0000x reference)
#include <cuda_runtime.h>
#include <cuda_fp16.h>
#include <cstdint>

// ===========================================================================
// GraphSAGE 3-layer forward, plain sm_100 target.
// R16 = R15 + layer-1 prep split: CSR-independent half (x->fp16 copy + W1
// transpose/convert) hoisted to s2 alongside W2/W3 conversions; s0 keeps only
// the CSR-dependent aggregate. Join moved to just before GEMM1.
// Single-product fp16 GEMM (legacy-HMMA ceiling), 3-stage cp.async, 2 CTA/SM;
// gathers forked concurrent with GEMM-b mainloops; layer-3 add fuses L2norm.
// ===========================================================================

#define NMAX 50000
#define DMAX 2048
#define EMAX 450000

static __device__ float g_P  [(long long)NMAX * DMAX];   // arena: P16 (fp16) + A2h (fp16)
static __device__ float g_AGG[(long long)NMAX * DMAX];   // arena: AGGh (fp16)
static __device__ float g_H  [(long long)NMAX * DMAX];   // arena: Hpre (fp16)
static __device__ int   g_cnt_i [NMAX];
static __device__ float g_invcnt[NMAX];
static __device__ int   g_rowptr[NMAX + 1];
static __device__ int   g_cursor[NMAX];
static __device__ int   g_csr   [EMAX];
static __device__ int   g_is64;

static __device__ __half g_Xh [(long long)NMAX * 256];
static __device__ __half g_A1h[(long long)NMAX * DMAX];
static __device__ __half g_W1 [2048 * 256];
static __device__ __half g_W2l[2048 * 2048];
static __device__ __half g_W2r[2048 * 2048];
static __device__ __half g_W3l[1024 * 2048];
static __device__ __half g_W3r[1024 * 2048];

// ---- aux stream/events, created at static-init (before harness baselines) --
struct Aux {
    cudaStream_t s2 = nullptr;
    cudaEvent_t evF = nullptr, evW = nullptr, evA = nullptr, evG = nullptr,
                evA2 = nullptr, evG2 = nullptr;
    bool ok = false;
    Aux() {
        ok = (cudaStreamCreateWithFlags(&s2, cudaStreamNonBlocking) == cudaSuccess) &&
             (cudaEventCreateWithFlags(&evF,  cudaEventDisableTiming) == cudaSuccess) &&
             (cudaEventCreateWithFlags(&evW,  cudaEventDisableTiming) == cudaSuccess) &&
             (cudaEventCreateWithFlags(&evA,  cudaEventDisableTiming) == cudaSuccess) &&
             (cudaEventCreateWithFlags(&evG,  cudaEventDisableTiming) == cudaSuccess) &&
             (cudaEventCreateWithFlags(&evA2, cudaEventDisableTiming) == cudaSuccess) &&
             (cudaEventCreateWithFlags(&evG2, cudaEventDisableTiming) == cudaSuccess);
        if (!ok) s2 = nullptr;   // degrade to serial on stream 0
    }
};
static Aux g_aux;

// ---------------- PTX helpers (sm_80-legal only) -----------------------------
__device__ __forceinline__ uint32_t smem_u32(const void* p) {
    uint32_t a;
    asm("{ .reg .u64 t; cvta.to.shared.u64 t, %1; cvt.u32.u64 %0, t; }" : "=r"(a) : "l"(p));
    return a;
}
#define CP_ASYNC16(dst, src) \
    asm volatile("cp.async.cg.shared.global [%0], [%1], 16;" :: "r"(dst), "l"(src) : "memory")
#define CP_COMMIT() asm volatile("cp.async.commit_group;" ::: "memory")
#define CP_WAIT(n)  asm volatile("cp.async.wait_group %0;" :: "n"(n) : "memory")
#define LDSM4(r, a)                                                                   \
    asm volatile("ldmatrix.sync.aligned.m8n8.x4.shared.b16 {%0,%1,%2,%3}, [%4];"      \
        : "=r"((r)[0]), "=r"((r)[1]), "=r"((r)[2]), "=r"((r)[3]) : "r"(a))
__device__ __forceinline__ void mma16816(float* c, const uint32_t* a, const uint32_t* b) {
    asm volatile(
        "mma.sync.aligned.m16n8k16.row.col.f32.f16.f16.f32 "
        "{%0,%1,%2,%3}, {%4,%5,%6,%7}, {%8,%9}, {%0,%1,%2,%3};"
        : "+f"(c[0]), "+f"(c[1]), "+f"(c[2]), "+f"(c[3])
        : "r"(a[0]), "r"(a[1]), "r"(a[2]), "r"(a[3]), "r"(b[0]), "r"(b[1]));
}

// ---------------- edge / CSR utils -------------------------------------------
__global__ void detect_zero_kernel(const int* __restrict__ w, int npairs, int N) {
    __shared__ int f;
    if (threadIdx.x == 0) f = 0;
    __syncthreads();
    for (int i = threadIdx.x; i < npairs; i += blockDim.x)
        if (w[2 * i + 1] != 0) f = 1;
    for (int i = threadIdx.x; i < N; i += blockDim.x) g_cnt_i[i] = 0;
    __syncthreads();
    if (threadIdx.x == 0) g_is64 = f ? 0 : 1;
}
__device__ __forceinline__ int edge_at(const void* ei, long long i, int is64) {
    return is64 ? (int)((const long long*)ei)[i] : ((const int*)ei)[i];
}
__global__ void count_deg_kernel(const void* __restrict__ ei, int E) {
    int e = blockIdx.x * blockDim.x + threadIdx.x;
    if (e >= E) return;
    atomicAdd(&g_cnt_i[edge_at(ei, (long long)E + e, g_is64)], 1);
}
__global__ void scan_inv_kernel(int N) {
    __shared__ int wsum[32];
    __shared__ int carry_s;
    const int tid = threadIdx.x, lane = tid & 31, w = tid >> 5;
    if (tid == 0) carry_s = 0;
    __syncthreads();
    for (int base = 0; base < N; base += 1024) {
        int v = (base + tid < N) ? g_cnt_i[base + tid] : 0;
        int s = v;
#pragma unroll
        for (int o = 1; o < 32; o <<= 1) {
            int t = __shfl_up_sync(0xFFFFFFFFu, s, o);
            if (lane >= o) s += t;
        }
        if (lane == 31) wsum[w] = s;
        __syncthreads();
        if (w == 0) {
            int t = wsum[lane];
#pragma unroll
            for (int o = 1; o < 32; o <<= 1) {
                int u = __shfl_up_sync(0xFFFFFFFFu, t, o);
                if (lane >= o) t += u;
            }
            wsum[lane] = t;
        }
        __syncthreads();
        const int excl = s - v + (w ? wsum[w - 1] : 0) + carry_s;
        if (base + tid < N) {
            g_rowptr[base + tid] = excl;
            g_cursor[base + tid] = excl;
            g_invcnt[base + tid] = 1.0f / (float)max(v, 1);
        }
        const int tot = wsum[31];
        __syncthreads();
        if (tid == 0) carry_s += tot;
        __syncthreads();
    }
    if (tid == 0) g_rowptr[N] = carry_s;
}
__global__ void fill_csr_kernel(const void* __restrict__ ei, int E) {
    int e = blockIdx.x * blockDim.x + threadIdx.x;
    if (e >= E) return;
    const int is64 = g_is64;
    const int s = edge_at(ei, e, is64);
    const int d = edge_at(ei, (long long)E + e, is64);
    g_csr[atomicAdd(&g_cursor[d], 1)] = s;
}
// AGGh[node,:] = invcnt[node] * sum_{src} S16[src,:]  (fp16 in, fp32 acc, fp16 out)
__global__ void gather_sum_h_kernel(const __half* __restrict__ S, __half* __restrict__ AGGh, int D) {
    const int node = blockIdx.x;
    const int col = threadIdx.x * 8;
    const int beg = g_rowptr[node], end = g_rowptr[node + 1];
    float acc[8];
#pragma unroll
    for (int j = 0; j < 8; j++) acc[j] = 0.f;
    const __half* base = S + col;
    int i = beg;
    for (; i + 4 <= end; i += 4) {
        const int s0 = g_csr[i], s1 = g_csr[i + 1], s2 = g_csr[i + 2], s3 = g_csr[i + 3];
        const uint4 v0 = *(const uint4*)(base + (long long)s0 * D);
        const uint4 v1 = *(const uint4*)(base + (long long)s1 * D);
        const uint4 v2 = *(const uint4*)(base + (long long)s2 * D);
        const uint4 v3 = *(const uint4*)(base + (long long)s3 * D);
        const __half2* h0 = (const __half2*)&v0;
        const __half2* h1 = (const __half2*)&v1;
        const __half2* h2 = (const __half2*)&v2;
        const __half2* h3 = (const __half2*)&v3;
#pragma unroll
        for (int j = 0; j < 4; j++) {
            float2 f0 = __half22float2(h0[j]), f1 = __half22float2(h1[j]);
            float2 f2 = __half22float2(h2[j]), f3 = __half22float2(h3[j]);
            acc[2 * j]     += (f0.x + f1.x) + (f2.x + f3.x);
            acc[2 * j + 1] += (f0.y + f1.y) + (f2.y + f3.y);
        }
    }
    for (; i < end; i++) {
        const uint4 v = *(const uint4*)(base + (long long)g_csr[i] * D);
        const __half2* h = (const __half2*)&v;
#pragma unroll
        for (int j = 0; j < 4; j++) {
            float2 f = __half22float2(h[j]);
            acc[2 * j]     += f.x;
            acc[2 * j + 1] += f.y;
        }
    }
    const float ic = g_invcnt[node];
    __half2 o[4];
#pragma unroll
    for (int j = 0; j < 4; j++)
        o[j] = __floats2half2_rn(acc[2 * j] * ic, acc[2 * j + 1] * ic);
    *(uint4*)(AGGh + (long long)node * D + col) = *(const uint4*)o;
}
// A2h = relu(Hpre + AGGh + bias)   elementwise, 8 halves/thread
__global__ void add_act_kernel(const __half* __restrict__ Hpre, const __half* __restrict__ AGGh,
                               const float* __restrict__ bias, __half* __restrict__ O,
                               long long total, int D) {
    const long long idx = ((long long)blockIdx.x * blockDim.x + threadIdx.x) * 8;
    if (idx >= total) return;
    const uint4 hv = *(const uint4*)(Hpre + idx);
    const uint4 av = *(const uint4*)(AGGh + idx);
    const int col = (int)(idx % D);
    const float4 b0 = *(const float4*)(bias + col);
    const float4 b1 = *(const float4*)(bias + col + 4);
    const float bb[8] = {b0.x, b0.y, b0.z, b0.w, b1.x, b1.y, b1.z, b1.w};
    const __half2* hh = (const __half2*)&hv;
    const __half2* aa = (const __half2*)&av;
    __half2 o[4];
#pragma unroll
    for (int j = 0; j < 4; j++) {
        float2 h = __half22float2(hh[j]);
        float2 a = __half22float2(aa[j]);
        float x = fmaxf(h.x + a.x + bb[2 * j], 0.f);
        float y = fmaxf(h.y + a.y + bb[2 * j + 1], 0.f);
        o[j] = __floats2half2_rn(x, y);
    }
    *(uint4*)(O + idx) = *(const uint4*)o;
}
// out[row,:] = l2norm(relu(Hpre[row,:] + AGGh[row,:] + bias))   block per row, D=1024
__global__ void add_act_norm_kernel(const __half* __restrict__ Hpre, const __half* __restrict__ AGGh,
                                    const float* __restrict__ bias, float* __restrict__ out, int D) {
    const int row = blockIdx.x;
    const int col = threadIdx.x * 4;
    const long long base = (long long)row * D + col;
    const float2 h0 = __half22float2(*(const __half2*)(Hpre + base));
    const float2 h1 = __half22float2(*(const __half2*)(Hpre + base + 2));
    const float2 a0 = __half22float2(*(const __half2*)(AGGh + base));
    const float2 a1 = __half22float2(*(const __half2*)(AGGh + base + 2));
    const float4 b = *(const float4*)(bias + col);
    float4 v;
    v.x = fmaxf(h0.x + a0.x + b.x, 0.f);
    v.y = fmaxf(h0.y + a0.y + b.y, 0.f);
    v.z = fmaxf(h1.x + a1.x + b.z, 0.f);
    v.w = fmaxf(h1.y + a1.y + b.w, 0.f);
    float s = v.x * v.x + v.y * v.y + v.z * v.z + v.w * v.w;
#pragma unroll
    for (int o = 16; o; o >>= 1) s += __shfl_xor_sync(0xFFFFFFFFu, s, o);
    __shared__ float ws[8];
    if ((threadIdx.x & 31) == 0) ws[threadIdx.x >> 5] = s;
    __syncthreads();
    if (threadIdx.x < 8) {
        float t = ws[threadIdx.x];
#pragma unroll
        for (int o = 4; o; o >>= 1) t += __shfl_xor_sync(0xFFu, t, o);
        if (threadIdx.x == 0) ws[0] = t;
    }
    __syncthreads();
    const float inv = 1.0f / fmaxf(sqrtf(ws[0]), 1e-12f);
    *(float4*)(out + base) = make_float4(v.x * inv, v.y * inv, v.z * inv, v.w * inv);
}

// ---------------- layer-1 prep: CSR-independent half (s2) --------------------
// blocks [0, xBlocks): Xh[r,128..255] = x[r,:] fp16  (32 threads/node, 8 nodes/blk)
// blocks [xBlocks, ...): W1 transpose/convert tiles
__global__ void l1x_kernel(const float* __restrict__ x, int N, int xBlocks,
                           const float* __restrict__ W1l, const float* __restrict__ W1r,
                           int F, int D1) {
    __shared__ float t[32][33];
    const int bid = blockIdx.x;
    if (bid < xBlocks) {
        const long long idx = (long long)bid * 256 + threadIdx.x;   // one per 4 floats
        const int node = (int)(idx >> 5);
        if (node >= N) return;
        const int col = (int)(idx & 31) * 4;
        const float4 v = *(const float4*)(x + (long long)node * 128 + col);
        __half2* dst = (__half2*)(g_Xh + (long long)node * 256 + 128 + col);
        dst[0] = __floats2half2_rn(v.x, v.y);
        dst[1] = __floats2half2_rn(v.z, v.w);
    } else {
        const int tI = bid - xBlocks;
        const int perMat = (D1 / 32) * (F / 32);
        const int mat = tI / perMat;               // 0 = W1l (kofs 0), 1 = W1r (kofs F)
        const int tile = tI % perMat;
        const int n0 = (tile % (D1 / 32)) * 32;
        const int k0 = (tile / (D1 / 32)) * 32;
        const float* W = mat ? W1r : W1l;
        const int kofs = mat ? F : 0;
        const int tx = threadIdx.x & 31, ty = threadIdx.x >> 5;   // 32 x 8
        for (int dy = ty; dy < 32; dy += 8)
            t[dy][tx] = W[(long long)(k0 + dy) * D1 + n0 + tx];
        __syncthreads();
        for (int dy = ty; dy < 32; dy += 8) {
            int n = n0 + dy, k = k0 + tx;
            g_W1[(long long)n * 256 + kofs + k] = __float2half_rn(t[tx][dy]);
        }
    }
}
// layer-1 aggregate half (s0, after CSR): Xh[r,0..127] = mean_x fp16
// 8 nodes x 32 lanes per 256-thread block
__global__ void l1_agg_kernel(const float* __restrict__ x, int N) {
    const int node = blockIdx.x * 8 + (threadIdx.x >> 5);
    if (node >= N) return;
    const int col = (threadIdx.x & 31) * 4;
    const int beg = g_rowptr[node], end = g_rowptr[node + 1];
    float4 acc = make_float4(0.f, 0.f, 0.f, 0.f);
    for (int i = beg; i < end; i++) {
        const float4 v = *(const float4*)(x + (long long)g_csr[i] * 128 + col);
        acc.x += v.x; acc.y += v.y; acc.z += v.z; acc.w += v.w;
    }
    const float ic = g_invcnt[node];
    __half2* dst = (__half2*)(g_Xh + (long long)node * 256 + col);
    dst[0] = __floats2half2_rn(acc.x * ic, acc.y * ic);
    dst[1] = __floats2half2_rn(acc.z * ic, acc.w * ic);
}
__global__ void wconvT_kernel(const float* __restrict__ W, __half* __restrict__ T,
                              int K, int N) {
    __shared__ float t[32][33];
    int n0 = blockIdx.x * 32, k0 = blockIdx.y * 32;
    for (int dy = threadIdx.y; dy < 32; dy += 8)
        t[dy][threadIdx.x] = W[(long long)(k0 + dy) * N + n0 + threadIdx.x];
    __syncthreads();
    for (int dy = threadIdx.y; dy < 32; dy += 8) {
        int n = n0 + dy, k = k0 + threadIdx.x;
        T[(long long)n * K + k] = __float2half_rn(t[threadIdx.x][dy]);
    }
}

// ---------------- mma.sync GEMM (single-product fp16) -------------------------
#define STG        3
#define STAGE_BY   32768              // A 16K | B 16K
#define SMEM_TOT   (STG * STAGE_BY)   // 96 KB -> 2 CTAs/SM

__global__ __launch_bounds__(256, 2)
void mma_gemm(const __half* __restrict__ A, const __half* __restrict__ B,
              __half* __restrict__ Oh, const __half* __restrict__ addmat16,
              const float* __restrict__ bias, int M, int Nc, int K, int relu) {
    extern __shared__ char sm[];
    const uint32_t sb = smem_u32(sm);
    const int tid = threadIdx.x, wid = tid >> 5, lane = tid & 31;
    const int m0 = blockIdx.y * 128, n0 = blockIdx.x * 128;
    const int nk = K >> 6;

    const int lrow = tid >> 1;
    const int u0   = (tid & 1) * 4;
    const bool arow_ok = (m0 + lrow) < M;
    const __half* gA = A + (long long)(m0 + lrow) * K;
    const __half* gB = B + (long long)(n0 + lrow) * K;
    uint32_t sst[4];
#pragma unroll
    for (int j = 0; j < 4; j++) {
        int u = u0 + j;
        sst[j] = lrow * 128 + ((u ^ (lrow & 7)) * 16);
    }

    float acc[4][4][4];
#pragma unroll
    for (int a = 0; a < 4; a++)
#pragma unroll
        for (int b = 0; b < 4; b++)
#pragma unroll
            for (int c = 0; c < 4; c++) acc[a][b][c] = 0.f;

    const int m0w = (wid & 1) * 64, n0w = (wid >> 1) * 32;

    auto issue = [&](int kt) {
        const uint32_t base = sb + (kt % STG) * STAGE_BY;
        const int k0 = kt * 64;
#pragma unroll
        for (int j = 0; j < 4; j++) {
            const int u = u0 + j;
            if (arow_ok) CP_ASYNC16(base + sst[j], gA + k0 + u * 8);
            CP_ASYNC16(base + 16384 + sst[j], gB + k0 + u * 8);
        }
        CP_COMMIT();
    };

    const int pro = nk < 2 ? nk : 2;
    for (int p = 0; p < pro; p++) issue(p);

    for (int kt = 0; kt < nk; kt++) {
        if (kt + 1 < nk) CP_WAIT(1);
        else             CP_WAIT(0);
        __syncthreads();                 // all warps done reading slot (kt-1)%3
        if (kt + 2 < nk) issue(kt + 2);  // refill that slot, overlapped w/ compute

        const uint32_t Ab = sb + (kt % STG) * STAGE_BY;
#pragma unroll
        for (int ks = 0; ks < 4; ks++) {
            uint32_t af[4][4];
#pragma unroll
            for (int mc = 0; mc < 4; mc++) {
                const int r = m0w + mc * 16 + (lane & 15);
                const int u = ks * 2 + (lane >> 4);
                LDSM4(af[mc], Ab + r * 128 + ((u ^ (r & 7)) * 16));
            }
            uint32_t bf[2][4];
#pragma unroll
            for (int pr = 0; pr < 2; pr++) {
                const int n = n0w + pr * 16 + ((lane >> 4) & 1) * 8 + (lane & 7);
                const int u = ks * 2 + ((lane >> 3) & 1);
                LDSM4(bf[pr], Ab + 16384 + n * 128 + ((u ^ (n & 7)) * 16));
            }
#pragma unroll
            for (int mc = 0; mc < 4; mc++)
#pragma unroll
                for (int pr = 0; pr < 2; pr++)
#pragma unroll
                    for (int h = 0; h < 2; h++)
                        mma16816(acc[mc][pr * 2 + h], af[mc], &bf[pr][h * 2]);
        }
    }

    // ---- fused epilogue (fp16 out) ----
#pragma unroll
    for (int mc = 0; mc < 4; mc++) {
#pragma unroll
        for (int half_ = 0; half_ < 2; half_++) {
            const int r = m0 + m0w + mc * 16 + (lane >> 2) + half_ * 8;
            if (r >= M) continue;
#pragma unroll
            for (int nc = 0; nc < 4; nc++) {
                const int col = n0 + n0w + nc * 8 + (lane & 3) * 2;
                float2 v = make_float2(acc[mc][nc][2 * half_], acc[mc][nc][2 * half_ + 1]);
                if (addmat16) {
                    const float2 a = __half22float2(*(const __half2*)(addmat16 + (long long)r * Nc + col));
                    v.x += a.x; v.y += a.y;
                }
                if (bias) {
                    const float2 bv = *(const float2*)(bias + col);
                    v.x += bv.x; v.y += bv.y;
                }
                if (relu) { v.x = fmaxf(v.x, 0.f); v.y = fmaxf(v.y, 0.f); }
                *(__half2*)(Oh + (long long)r * Nc + col) = __floats2half2_rn(v.x, v.y);
            }
        }
    }
}

// ---------------- host -------------------------------------------------------
static void run_mma(const __half* A, const __half* B, __half* Oh,
                    const __half* addmat16, const float* bias,
                    int M, int Nc, int K, int relu, cudaStream_t st) {
    static bool attr_set = false;
    if (!attr_set) {
        cudaFuncSetAttribute(mma_gemm, cudaFuncAttributeMaxDynamicSharedMemorySize, SMEM_TOT);
        attr_set = true;
    }
    dim3 grid(Nc / 128, (M + 127) / 128);
    mma_gemm<<<grid, 256, SMEM_TOT, st>>>(A, B, Oh, addmat16, bias, M, Nc, K, relu);
}

extern "C" void kernel_launch(void* const* d_in, const int* in_sizes, int n_in,
                              void* d_out, int out_size) {
    const float* x   = (const float*)d_in[0];
    const void*  ei  = d_in[2];
    const float* W1l = (const float*)d_in[3];
    const float* W1r = (const float*)d_in[4];
    const float* b1  = (const float*)d_in[5];
    const float* W2l = (const float*)d_in[6];
    const float* W2r = (const float*)d_in[7];
    const float* b2  = (const float*)d_in[8];
    const float* W3l = (const float*)d_in[9];
    const float* W3r = (const float*)d_in[10];
    const float* b3  = (const float*)d_in[11];

    const int D1 = in_sizes[5];       // 2048
    const int D2 = in_sizes[8];       // 2048
    const int D3 = in_sizes[11];      // 1024
    const int F  = in_sizes[3] / D1;  // 128
    const int N  = in_sizes[0] / F;   // 50000
    const int E  = in_sizes[2] / 2;   // 400000

    float *P, *AGG, *H;
    cudaGetSymbolAddress((void**)&P, g_P);
    cudaGetSymbolAddress((void**)&AGG, g_AGG);
    cudaGetSymbolAddress((void**)&H, g_H);
    __half *Xh, *A1h, *W1, *W2lp, *W2rp, *W3lp, *W3rp;
    cudaGetSymbolAddress((void**)&Xh, g_Xh);
    cudaGetSymbolAddress((void**)&A1h, g_A1h);
    cudaGetSymbolAddress((void**)&W1, g_W1);
    cudaGetSymbolAddress((void**)&W2lp, g_W2l);
    cudaGetSymbolAddress((void**)&W2rp, g_W2r);
    cudaGetSymbolAddress((void**)&W3lp, g_W3l);
    cudaGetSymbolAddress((void**)&W3rp, g_W3r);

    __half* P16  = (__half*)P;
    __half* A2h  = P16 + (long long)N * D2;
    __half* AGGh = (__half*)AGG;
    __half* Hpre = (__half*)H;

    float* out = (float*)d_out;
    const int TPB = 256;
    const int eb = (E + TPB - 1) / TPB;
    cudaStream_t s0 = 0;
    const bool fork = g_aux.ok;
    dim3 tb(32, 8);

    const int xBlocks = (N * 32 + 255) / 256;          // x->fp16 copy blocks
    const int w1Tiles = 2 * (D1 / 32) * (F / 32);

    // ---- fork s2 from s0 (root event first), hoist CSR-independent prep ----
    if (fork) {
        cudaEventRecord(g_aux.evF, s0);
        cudaStreamWaitEvent(g_aux.s2, g_aux.evF, 0);
        wconvT_kernel<<<dim3(D2 / 32, D1 / 32), tb, 0, g_aux.s2>>>(W2l, W2lp, D1, D2);
        wconvT_kernel<<<dim3(D2 / 32, D1 / 32), tb, 0, g_aux.s2>>>(W2r, W2rp, D1, D2);
        wconvT_kernel<<<dim3(D3 / 32, D2 / 32), tb, 0, g_aux.s2>>>(W3l, W3lp, D2, D3);
        wconvT_kernel<<<dim3(D3 / 32, D2 / 32), tb, 0, g_aux.s2>>>(W3r, W3rp, D2, D3);
        l1x_kernel<<<xBlocks + w1Tiles, 256, 0, g_aux.s2>>>(x, N, xBlocks, W1l, W1r, F, D1);
        cudaEventRecord(g_aux.evW, g_aux.s2);
    }

    // ---- prologue (s0) ----
    detect_zero_kernel<<<1, 256, 0, s0>>>((const int*)ei, E < 1024 ? E : 1024, N);
    count_deg_kernel<<<eb, TPB, 0, s0>>>(ei, E);
    scan_inv_kernel<<<1, 1024, 0, s0>>>(N);
    fill_csr_kernel<<<eb, TPB, 0, s0>>>(ei, E);

    // ---- layer-1 aggregate (CSR-dependent) ----
    l1_agg_kernel<<<(N + 7) / 8, 256, 0, s0>>>(x, N);
    if (fork) {
        cudaStreamWaitEvent(s0, g_aux.evW, 0);   // Xh copy + W1 + W2/W3 ready
    } else {
        wconvT_kernel<<<dim3(D2 / 32, D1 / 32), tb, 0, s0>>>(W2l, W2lp, D1, D2);
        wconvT_kernel<<<dim3(D2 / 32, D1 / 32), tb, 0, s0>>>(W2r, W2rp, D1, D2);
        wconvT_kernel<<<dim3(D3 / 32, D2 / 32), tb, 0, s0>>>(W3l, W3lp, D2, D3);
        wconvT_kernel<<<dim3(D3 / 32, D2 / 32), tb, 0, s0>>>(W3r, W3rp, D2, D3);
        l1x_kernel<<<xBlocks + w1Tiles, 256, 0, s0>>>(x, N, xBlocks, W1l, W1r, F, D1);
    }
    run_mma(Xh, W1, A1h, nullptr, b1, N, D1, 2 * F, 1, s0);

    // ---- layer 2: P16 = H1@W2l; fork gather || Hpre = H1@W2r; join; add ----
    run_mma(A1h, W2lp, P16, nullptr, nullptr, N, D2, D1, 0, s0);
    if (fork) {
        cudaEventRecord(g_aux.evA, s0);
        cudaStreamWaitEvent(g_aux.s2, g_aux.evA, 0);
        gather_sum_h_kernel<<<N, D2 / 8, 0, g_aux.s2>>>(P16, AGGh, D2);
        cudaEventRecord(g_aux.evG, g_aux.s2);
        run_mma(A1h, W2rp, Hpre, nullptr, nullptr, N, D2, D1, 0, s0);
        cudaStreamWaitEvent(s0, g_aux.evG, 0);
    } else {
        gather_sum_h_kernel<<<N, D2 / 8, 0, s0>>>(P16, AGGh, D2);
        run_mma(A1h, W2rp, Hpre, nullptr, nullptr, N, D2, D1, 0, s0);
    }
    {
        const long long tot = (long long)N * D2;
        add_act_kernel<<<(int)((tot / 8 + TPB - 1) / TPB), TPB, 0, s0>>>(Hpre, AGGh, b2, A2h, tot, D2);
    }

    // ---- layer 3: P16 = H2@W3l; fork gather || Hpre = H2@W3r; join; add+norm ----
    run_mma(A2h, W3lp, P16, nullptr, nullptr, N, D3, D2, 0, s0);
    if (fork) {
        cudaEventRecord(g_aux.evA2, s0);
        cudaStreamWaitEvent(g_aux.s2, g_aux.evA2, 0);
        gather_sum_h_kernel<<<N, D3 / 8, 0, g_aux.s2>>>(P16, AGGh, D3);
        cudaEventRecord(g_aux.evG2, g_aux.s2);
        run_mma(A2h, W3rp, Hpre, nullptr, nullptr, N, D3, D2, 0, s0);
        cudaStreamWaitEvent(s0, g_aux.evG2, 0);
    } else {
        gather_sum_h_kernel<<<N, D3 / 8, 0, s0>>>(P16, AGGh, D3);
        run_mma(A2h, W3rp, Hpre, nullptr, nullptr, N, D3, D2, 0, s0);
    }
    add_act_norm_kernel<<<N, D3 / 4, 0, s0>>>(Hpre, AGGh, b3, out, D3);

    (void)n_in; (void)out_size;
}

// round 17
// speedup vs baseline: 1.0030x; 1.0030x over previous
#include <cuda_runtime.h>
#include <cuda_fp16.h>
#include <cstdint>

// ===========================================================================
// GraphSAGE 3-layer forward, plain sm_100 target.
// R17 = R15 (best measured) + M-split pipelining of the add kernels:
// GEMM-b is launched as two M-halves; add-half-1 runs on s2 concurrent with
// GEMM-b half-2 (BW-bound add overlaps HMMA-bound GEMM). Only add-half-2
// remains serial. Gathers remain forked under GEMM-b; weight conversions
// remain hoisted to s2 under the prologue+GEMM1.
// Single-product fp16 GEMM (legacy-HMMA ceiling), 3-stage cp.async, 2 CTA/SM.
// ===========================================================================

#define NMAX 50000
#define DMAX 2048
#define EMAX 450000

static __device__ float g_P  [(long long)NMAX * DMAX];   // arena: P16 (fp16) + A2h (fp16)
static __device__ float g_AGG[(long long)NMAX * DMAX];   // arena: AGGh (fp16)
static __device__ float g_H  [(long long)NMAX * DMAX];   // arena: Hpre (fp16)
static __device__ int   g_cnt_i [NMAX];
static __device__ float g_invcnt[NMAX];
static __device__ int   g_rowptr[NMAX + 1];
static __device__ int   g_cursor[NMAX];
static __device__ int   g_csr   [EMAX];
static __device__ int   g_is64;

static __device__ __half g_Xh [(long long)NMAX * 256];
static __device__ __half g_A1h[(long long)NMAX * DMAX];
static __device__ __half g_W1 [2048 * 256];
static __device__ __half g_W2l[2048 * 2048];
static __device__ __half g_W2r[2048 * 2048];
static __device__ __half g_W3l[1024 * 2048];
static __device__ __half g_W3r[1024 * 2048];

// ---- aux stream/events, created at static-init (before harness baselines) --
struct Aux {
    cudaStream_t s2 = nullptr;
    cudaEvent_t evF = nullptr, evW = nullptr, evA = nullptr, evG = nullptr,
                evA2 = nullptr, evG2 = nullptr,
                evH1 = nullptr, evD1 = nullptr, evH1b = nullptr, evN1 = nullptr;
    bool ok = false;
    Aux() {
        ok = (cudaStreamCreateWithFlags(&s2, cudaStreamNonBlocking) == cudaSuccess) &&
             (cudaEventCreateWithFlags(&evF,   cudaEventDisableTiming) == cudaSuccess) &&
             (cudaEventCreateWithFlags(&evW,   cudaEventDisableTiming) == cudaSuccess) &&
             (cudaEventCreateWithFlags(&evA,   cudaEventDisableTiming) == cudaSuccess) &&
             (cudaEventCreateWithFlags(&evG,   cudaEventDisableTiming) == cudaSuccess) &&
             (cudaEventCreateWithFlags(&evA2,  cudaEventDisableTiming) == cudaSuccess) &&
             (cudaEventCreateWithFlags(&evG2,  cudaEventDisableTiming) == cudaSuccess) &&
             (cudaEventCreateWithFlags(&evH1,  cudaEventDisableTiming) == cudaSuccess) &&
             (cudaEventCreateWithFlags(&evD1,  cudaEventDisableTiming) == cudaSuccess) &&
             (cudaEventCreateWithFlags(&evH1b, cudaEventDisableTiming) == cudaSuccess) &&
             (cudaEventCreateWithFlags(&evN1,  cudaEventDisableTiming) == cudaSuccess);
        if (!ok) s2 = nullptr;   // degrade to serial on stream 0
    }
};
static Aux g_aux;

// ---------------- PTX helpers (sm_80-legal only) -----------------------------
__device__ __forceinline__ uint32_t smem_u32(const void* p) {
    uint32_t a;
    asm("{ .reg .u64 t; cvta.to.shared.u64 t, %1; cvt.u32.u64 %0, t; }" : "=r"(a) : "l"(p));
    return a;
}
#define CP_ASYNC16(dst, src) \
    asm volatile("cp.async.cg.shared.global [%0], [%1], 16;" :: "r"(dst), "l"(src) : "memory")
#define CP_COMMIT() asm volatile("cp.async.commit_group;" ::: "memory")
#define CP_WAIT(n)  asm volatile("cp.async.wait_group %0;" :: "n"(n) : "memory")
#define LDSM4(r, a)                                                                   \
    asm volatile("ldmatrix.sync.aligned.m8n8.x4.shared.b16 {%0,%1,%2,%3}, [%4];"      \
        : "=r"((r)[0]), "=r"((r)[1]), "=r"((r)[2]), "=r"((r)[3]) : "r"(a))
__device__ __forceinline__ void mma16816(float* c, const uint32_t* a, const uint32_t* b) {
    asm volatile(
        "mma.sync.aligned.m16n8k16.row.col.f32.f16.f16.f32 "
        "{%0,%1,%2,%3}, {%4,%5,%6,%7}, {%8,%9}, {%0,%1,%2,%3};"
        : "+f"(c[0]), "+f"(c[1]), "+f"(c[2]), "+f"(c[3])
        : "r"(a[0]), "r"(a[1]), "r"(a[2]), "r"(a[3]), "r"(b[0]), "r"(b[1]));
}

// ---------------- edge / CSR utils -------------------------------------------
__global__ void detect_zero_kernel(const int* __restrict__ w, int npairs, int N) {
    __shared__ int f;
    if (threadIdx.x == 0) f = 0;
    __syncthreads();
    for (int i = threadIdx.x; i < npairs; i += blockDim.x)
        if (w[2 * i + 1] != 0) f = 1;
    for (int i = threadIdx.x; i < N; i += blockDim.x) g_cnt_i[i] = 0;
    __syncthreads();
    if (threadIdx.x == 0) g_is64 = f ? 0 : 1;
}
__device__ __forceinline__ int edge_at(const void* ei, long long i, int is64) {
    return is64 ? (int)((const long long*)ei)[i] : ((const int*)ei)[i];
}
__global__ void count_deg_kernel(const void* __restrict__ ei, int E) {
    int e = blockIdx.x * blockDim.x + threadIdx.x;
    if (e >= E) return;
    atomicAdd(&g_cnt_i[edge_at(ei, (long long)E + e, g_is64)], 1);
}
__global__ void scan_inv_kernel(int N) {
    __shared__ int wsum[32];
    __shared__ int carry_s;
    const int tid = threadIdx.x, lane = tid & 31, w = tid >> 5;
    if (tid == 0) carry_s = 0;
    __syncthreads();
    for (int base = 0; base < N; base += 1024) {
        int v = (base + tid < N) ? g_cnt_i[base + tid] : 0;
        int s = v;
#pragma unroll
        for (int o = 1; o < 32; o <<= 1) {
            int t = __shfl_up_sync(0xFFFFFFFFu, s, o);
            if (lane >= o) s += t;
        }
        if (lane == 31) wsum[w] = s;
        __syncthreads();
        if (w == 0) {
            int t = wsum[lane];
#pragma unroll
            for (int o = 1; o < 32; o <<= 1) {
                int u = __shfl_up_sync(0xFFFFFFFFu, t, o);
                if (lane >= o) t += u;
            }
            wsum[lane] = t;
        }
        __syncthreads();
        const int excl = s - v + (w ? wsum[w - 1] : 0) + carry_s;
        if (base + tid < N) {
            g_rowptr[base + tid] = excl;
            g_cursor[base + tid] = excl;
            g_invcnt[base + tid] = 1.0f / (float)max(v, 1);
        }
        const int tot = wsum[31];
        __syncthreads();
        if (tid == 0) carry_s += tot;
        __syncthreads();
    }
    if (tid == 0) g_rowptr[N] = carry_s;
}
__global__ void fill_csr_kernel(const void* __restrict__ ei, int E) {
    int e = blockIdx.x * blockDim.x + threadIdx.x;
    if (e >= E) return;
    const int is64 = g_is64;
    const int s = edge_at(ei, e, is64);
    const int d = edge_at(ei, (long long)E + e, is64);
    g_csr[atomicAdd(&g_cursor[d], 1)] = s;
}
// AGGh[node,:] = invcnt[node] * sum_{src} S16[src,:]  (fp16 in, fp32 acc, fp16 out)
__global__ void gather_sum_h_kernel(const __half* __restrict__ S, __half* __restrict__ AGGh, int D) {
    const int node = blockIdx.x;
    const int col = threadIdx.x * 8;
    const int beg = g_rowptr[node], end = g_rowptr[node + 1];
    float acc[8];
#pragma unroll
    for (int j = 0; j < 8; j++) acc[j] = 0.f;
    const __half* base = S + col;
    int i = beg;
    for (; i + 4 <= end; i += 4) {
        const int s0 = g_csr[i], s1 = g_csr[i + 1], s2 = g_csr[i + 2], s3 = g_csr[i + 3];
        const uint4 v0 = *(const uint4*)(base + (long long)s0 * D);
        const uint4 v1 = *(const uint4*)(base + (long long)s1 * D);
        const uint4 v2 = *(const uint4*)(base + (long long)s2 * D);
        const uint4 v3 = *(const uint4*)(base + (long long)s3 * D);
        const __half2* h0 = (const __half2*)&v0;
        const __half2* h1 = (const __half2*)&v1;
        const __half2* h2 = (const __half2*)&v2;
        const __half2* h3 = (const __half2*)&v3;
#pragma unroll
        for (int j = 0; j < 4; j++) {
            float2 f0 = __half22float2(h0[j]), f1 = __half22float2(h1[j]);
            float2 f2 = __half22float2(h2[j]), f3 = __half22float2(h3[j]);
            acc[2 * j]     += (f0.x + f1.x) + (f2.x + f3.x);
            acc[2 * j + 1] += (f0.y + f1.y) + (f2.y + f3.y);
        }
    }
    for (; i < end; i++) {
        const uint4 v = *(const uint4*)(base + (long long)g_csr[i] * D);
        const __half2* h = (const __half2*)&v;
#pragma unroll
        for (int j = 0; j < 4; j++) {
            float2 f = __half22float2(h[j]);
            acc[2 * j]     += f.x;
            acc[2 * j + 1] += f.y;
        }
    }
    const float ic = g_invcnt[node];
    __half2 o[4];
#pragma unroll
    for (int j = 0; j < 4; j++)
        o[j] = __floats2half2_rn(acc[2 * j] * ic, acc[2 * j + 1] * ic);
    *(uint4*)(AGGh + (long long)node * D + col) = *(const uint4*)o;
}
// O = relu(Hpre + AGGh + bias)   elementwise (row-range via offset ptrs)
__global__ void add_act_kernel(const __half* __restrict__ Hpre, const __half* __restrict__ AGGh,
                               const float* __restrict__ bias, __half* __restrict__ O,
                               long long total, int D) {
    const long long idx = ((long long)blockIdx.x * blockDim.x + threadIdx.x) * 8;
    if (idx >= total) return;
    const uint4 hv = *(const uint4*)(Hpre + idx);
    const uint4 av = *(const uint4*)(AGGh + idx);
    const int col = (int)(idx % D);
    const float4 b0 = *(const float4*)(bias + col);
    const float4 b1 = *(const float4*)(bias + col + 4);
    const float bb[8] = {b0.x, b0.y, b0.z, b0.w, b1.x, b1.y, b1.z, b1.w};
    const __half2* hh = (const __half2*)&hv;
    const __half2* aa = (const __half2*)&av;
    __half2 o[4];
#pragma unroll
    for (int j = 0; j < 4; j++) {
        float2 h = __half22float2(hh[j]);
        float2 a = __half22float2(aa[j]);
        float x = fmaxf(h.x + a.x + bb[2 * j], 0.f);
        float y = fmaxf(h.y + a.y + bb[2 * j + 1], 0.f);
        o[j] = __floats2half2_rn(x, y);
    }
    *(uint4*)(O + idx) = *(const uint4*)o;
}
// out[row,:] = l2norm(relu(Hpre[row,:] + AGGh[row,:] + bias)); row-range via ptrs
__global__ void add_act_norm_kernel(const __half* __restrict__ Hpre, const __half* __restrict__ AGGh,
                                    const float* __restrict__ bias, float* __restrict__ out, int D) {
    const int row = blockIdx.x;
    const int col = threadIdx.x * 4;
    const long long base = (long long)row * D + col;
    const float2 h0 = __half22float2(*(const __half2*)(Hpre + base));
    const float2 h1 = __half22float2(*(const __half2*)(Hpre + base + 2));
    const float2 a0 = __half22float2(*(const __half2*)(AGGh + base));
    const float2 a1 = __half22float2(*(const __half2*)(AGGh + base + 2));
    const float4 b = *(const float4*)(bias + col);
    float4 v;
    v.x = fmaxf(h0.x + a0.x + b.x, 0.f);
    v.y = fmaxf(h0.y + a0.y + b.y, 0.f);
    v.z = fmaxf(h1.x + a1.x + b.z, 0.f);
    v.w = fmaxf(h1.y + a1.y + b.w, 0.f);
    float s = v.x * v.x + v.y * v.y + v.z * v.z + v.w * v.w;
#pragma unroll
    for (int o = 16; o; o >>= 1) s += __shfl_xor_sync(0xFFFFFFFFu, s, o);
    __shared__ float ws[8];
    if ((threadIdx.x & 31) == 0) ws[threadIdx.x >> 5] = s;
    __syncthreads();
    if (threadIdx.x < 8) {
        float t = ws[threadIdx.x];
#pragma unroll
        for (int o = 4; o; o >>= 1) t += __shfl_xor_sync(0xFFu, t, o);
        if (threadIdx.x == 0) ws[0] = t;
    }
    __syncthreads();
    const float inv = 1.0f / fmaxf(sqrtf(ws[0]), 1e-12f);
    *(float4*)(out + base) = make_float4(v.x * inv, v.y * inv, v.z * inv, v.w * inv);
}

// ---------------- layer-1 prep + weight conversion ---------------------------
__global__ void l1_prep_kernel(const float* __restrict__ x, int N, int nodeBlocks,
                               const float* __restrict__ W1l, const float* __restrict__ W1r,
                               int F, int D1) {
    __shared__ float t[32][33];
    const int bid = blockIdx.x;
    if (bid < nodeBlocks) {
        const int sub = threadIdx.x >> 6;          // 0..3
        const int st  = threadIdx.x & 63;          // 0..63
        const int node = bid * 4 + sub;
        if (node >= N) return;
        if (st < 32) {
            const int col = st * 4;
            const int beg = g_rowptr[node], end = g_rowptr[node + 1];
            float4 acc = make_float4(0.f, 0.f, 0.f, 0.f);
            for (int i = beg; i < end; i++) {
                const float4 v = *(const float4*)(x + (long long)g_csr[i] * 128 + col);
                acc.x += v.x; acc.y += v.y; acc.z += v.z; acc.w += v.w;
            }
            const float ic = g_invcnt[node];
            __half2* dst = (__half2*)(g_Xh + (long long)node * 256 + col);
            dst[0] = __floats2half2_rn(acc.x * ic, acc.y * ic);
            dst[1] = __floats2half2_rn(acc.z * ic, acc.w * ic);
        } else {
            const int col = (st - 32) * 4;
            const float4 v = *(const float4*)(x + (long long)node * 128 + col);
            __half2* dst = (__half2*)(g_Xh + (long long)node * 256 + 128 + col);
            dst[0] = __floats2half2_rn(v.x, v.y);
            dst[1] = __floats2half2_rn(v.z, v.w);
        }
    } else {
        const int tI = bid - nodeBlocks;
        const int perMat = (D1 / 32) * (F / 32);
        const int mat = tI / perMat;               // 0 = W1l (kofs 0), 1 = W1r (kofs F)
        const int tile = tI % perMat;
        const int n0 = (tile % (D1 / 32)) * 32;
        const int k0 = (tile / (D1 / 32)) * 32;
        const float* W = mat ? W1r : W1l;
        const int kofs = mat ? F : 0;
        const int tx = threadIdx.x & 31, ty = threadIdx.x >> 5;   // 32 x 8
        for (int dy = ty; dy < 32; dy += 8)
            t[dy][tx] = W[(long long)(k0 + dy) * D1 + n0 + tx];
        __syncthreads();
        for (int dy = ty; dy < 32; dy += 8) {
            int n = n0 + dy, k = k0 + tx;
            g_W1[(long long)n * 256 + kofs + k] = __float2half_rn(t[tx][dy]);
        }
    }
}
__global__ void wconvT_kernel(const float* __restrict__ W, __half* __restrict__ T,
                              int K, int N) {
    __shared__ float t[32][33];
    int n0 = blockIdx.x * 32, k0 = blockIdx.y * 32;
    for (int dy = threadIdx.y; dy < 32; dy += 8)
        t[dy][threadIdx.x] = W[(long long)(k0 + dy) * N + n0 + threadIdx.x];
    __syncthreads();
    for (int dy = threadIdx.y; dy < 32; dy += 8) {
        int n = n0 + dy, k = k0 + threadIdx.x;
        T[(long long)n * K + k] = __float2half_rn(t[threadIdx.x][dy]);
    }
}

// ---------------- mma.sync GEMM (single-product fp16) -------------------------
#define STG        3
#define STAGE_BY   32768              // A 16K | B 16K
#define SMEM_TOT   (STG * STAGE_BY)   // 96 KB -> 2 CTAs/SM

__global__ __launch_bounds__(256, 2)
void mma_gemm(const __half* __restrict__ A, const __half* __restrict__ B,
              __half* __restrict__ Oh, const __half* __restrict__ addmat16,
              const float* __restrict__ bias, int M, int Nc, int K, int relu) {
    extern __shared__ char sm[];
    const uint32_t sb = smem_u32(sm);
    const int tid = threadIdx.x, wid = tid >> 5, lane = tid & 31;
    const int m0 = blockIdx.y * 128, n0 = blockIdx.x * 128;
    const int nk = K >> 6;

    const int lrow = tid >> 1;
    const int u0   = (tid & 1) * 4;
    const bool arow_ok = (m0 + lrow) < M;
    const __half* gA = A + (long long)(m0 + lrow) * K;
    const __half* gB = B + (long long)(n0 + lrow) * K;
    uint32_t sst[4];
#pragma unroll
    for (int j = 0; j < 4; j++) {
        int u = u0 + j;
        sst[j] = lrow * 128 + ((u ^ (lrow & 7)) * 16);
    }

    float acc[4][4][4];
#pragma unroll
    for (int a = 0; a < 4; a++)
#pragma unroll
        for (int b = 0; b < 4; b++)
#pragma unroll
            for (int c = 0; c < 4; c++) acc[a][b][c] = 0.f;

    const int m0w = (wid & 1) * 64, n0w = (wid >> 1) * 32;

    auto issue = [&](int kt) {
        const uint32_t base = sb + (kt % STG) * STAGE_BY;
        const int k0 = kt * 64;
#pragma unroll
        for (int j = 0; j < 4; j++) {
            const int u = u0 + j;
            if (arow_ok) CP_ASYNC16(base + sst[j], gA + k0 + u * 8);
            CP_ASYNC16(base + 16384 + sst[j], gB + k0 + u * 8);
        }
        CP_COMMIT();
    };

    const int pro = nk < 2 ? nk : 2;
    for (int p = 0; p < pro; p++) issue(p);

    for (int kt = 0; kt < nk; kt++) {
        if (kt + 1 < nk) CP_WAIT(1);
        else             CP_WAIT(0);
        __syncthreads();                 // all warps done reading slot (kt-1)%3
        if (kt + 2 < nk) issue(kt + 2);  // refill that slot, overlapped w/ compute

        const uint32_t Ab = sb + (kt % STG) * STAGE_BY;
#pragma unroll
        for (int ks = 0; ks < 4; ks++) {
            uint32_t af[4][4];
#pragma unroll
            for (int mc = 0; mc < 4; mc++) {
                const int r = m0w + mc * 16 + (lane & 15);
                const int u = ks * 2 + (lane >> 4);
                LDSM4(af[mc], Ab + r * 128 + ((u ^ (r & 7)) * 16));
            }
            uint32_t bf[2][4];
#pragma unroll
            for (int pr = 0; pr < 2; pr++) {
                const int n = n0w + pr * 16 + ((lane >> 4) & 1) * 8 + (lane & 7);
                const int u = ks * 2 + ((lane >> 3) & 1);
                LDSM4(bf[pr], Ab + 16384 + n * 128 + ((u ^ (n & 7)) * 16));
            }
#pragma unroll
            for (int mc = 0; mc < 4; mc++)
#pragma unroll
                for (int pr = 0; pr < 2; pr++)
#pragma unroll
                    for (int h = 0; h < 2; h++)
                        mma16816(acc[mc][pr * 2 + h], af[mc], &bf[pr][h * 2]);
        }
    }

    // ---- fused epilogue (fp16 out) ----
#pragma unroll
    for (int mc = 0; mc < 4; mc++) {
#pragma unroll
        for (int half_ = 0; half_ < 2; half_++) {
            const int r = m0 + m0w + mc * 16 + (lane >> 2) + half_ * 8;
            if (r >= M) continue;
#pragma unroll
            for (int nc = 0; nc < 4; nc++) {
                const int col = n0 + n0w + nc * 8 + (lane & 3) * 2;
                float2 v = make_float2(acc[mc][nc][2 * half_], acc[mc][nc][2 * half_ + 1]);
                if (addmat16) {
                    const float2 a = __half22float2(*(const __half2*)(addmat16 + (long long)r * Nc + col));
                    v.x += a.x; v.y += a.y;
                }
                if (bias) {
                    const float2 bv = *(const float2*)(bias + col);
                    v.x += bv.x; v.y += bv.y;
                }
                if (relu) { v.x = fmaxf(v.x, 0.f); v.y = fmaxf(v.y, 0.f); }
                *(__half2*)(Oh + (long long)r * Nc + col) = __floats2half2_rn(v.x, v.y);
            }
        }
    }
}

// ---------------- host -------------------------------------------------------
static void run_mma(const __half* A, const __half* B, __half* Oh,
                    const __half* addmat16, const float* bias,
                    int M, int Nc, int K, int relu, cudaStream_t st) {
    static bool attr_set = false;
    if (!attr_set) {
        cudaFuncSetAttribute(mma_gemm, cudaFuncAttributeMaxDynamicSharedMemorySize, SMEM_TOT);
        attr_set = true;
    }
    dim3 grid(Nc / 128, (M + 127) / 128);
    mma_gemm<<<grid, 256, SMEM_TOT, st>>>(A, B, Oh, addmat16, bias, M, Nc, K, relu);
}

extern "C" void kernel_launch(void* const* d_in, const int* in_sizes, int n_in,
                              void* d_out, int out_size) {
    const float* x   = (const float*)d_in[0];
    const void*  ei  = d_in[2];
    const float* W1l = (const float*)d_in[3];
    const float* W1r = (const float*)d_in[4];
    const float* b1  = (const float*)d_in[5];
    const float* W2l = (const float*)d_in[6];
    const float* W2r = (const float*)d_in[7];
    const float* b2  = (const float*)d_in[8];
    const float* W3l = (const float*)d_in[9];
    const float* W3r = (const float*)d_in[10];
    const float* b3  = (const float*)d_in[11];

    const int D1 = in_sizes[5];       // 2048
    const int D2 = in_sizes[8];       // 2048
    const int D3 = in_sizes[11];      // 1024
    const int F  = in_sizes[3] / D1;  // 128
    const int N  = in_sizes[0] / F;   // 50000
    const int E  = in_sizes[2] / 2;   // 400000

    float *P, *AGG, *H;
    cudaGetSymbolAddress((void**)&P, g_P);
    cudaGetSymbolAddress((void**)&AGG, g_AGG);
    cudaGetSymbolAddress((void**)&H, g_H);
    __half *Xh, *A1h, *W1, *W2lp, *W2rp, *W3lp, *W3rp;
    cudaGetSymbolAddress((void**)&Xh, g_Xh);
    cudaGetSymbolAddress((void**)&A1h, g_A1h);
    cudaGetSymbolAddress((void**)&W1, g_W1);
    cudaGetSymbolAddress((void**)&W2lp, g_W2l);
    cudaGetSymbolAddress((void**)&W2rp, g_W2r);
    cudaGetSymbolAddress((void**)&W3lp, g_W3l);
    cudaGetSymbolAddress((void**)&W3rp, g_W3r);

    __half* P16  = (__half*)P;
    __half* A2h  = P16 + (long long)N * D2;
    __half* AGGh = (__half*)AGG;
    __half* Hpre = (__half*)H;

    float* out = (float*)d_out;
    const int TPB = 256;
    const int eb = (E + TPB - 1) / TPB;
    cudaStream_t s0 = 0;
    const bool fork = g_aux.ok;
    dim3 tb(32, 8);

    // M split: half-1 rounded to a 128-row tile boundary
    const int M1 = (((N + 127) / 128 + 1) / 2) * 128;   // 25088
    const int M2 = N - M1;                              // 24912

    // ---- fork s2 from s0 (root event first), hoist weight conversions ----
    if (fork) {
        cudaEventRecord(g_aux.evF, s0);
        cudaStreamWaitEvent(g_aux.s2, g_aux.evF, 0);
        wconvT_kernel<<<dim3(D2 / 32, D1 / 32), tb, 0, g_aux.s2>>>(W2l, W2lp, D1, D2);
        wconvT_kernel<<<dim3(D2 / 32, D1 / 32), tb, 0, g_aux.s2>>>(W2r, W2rp, D1, D2);
        wconvT_kernel<<<dim3(D3 / 32, D2 / 32), tb, 0, g_aux.s2>>>(W3l, W3lp, D2, D3);
        wconvT_kernel<<<dim3(D3 / 32, D2 / 32), tb, 0, g_aux.s2>>>(W3r, W3rp, D2, D3);
        cudaEventRecord(g_aux.evW, g_aux.s2);
    }

    // ---- prologue (s0) ----
    detect_zero_kernel<<<1, 256, 0, s0>>>((const int*)ei, E < 1024 ? E : 1024, N);
    count_deg_kernel<<<eb, TPB, 0, s0>>>(ei, E);
    scan_inv_kernel<<<1, 1024, 0, s0>>>(N);
    fill_csr_kernel<<<eb, TPB, 0, s0>>>(ei, E);

    // ---- layer 1 prep + GEMM1 ----
    const int nodeBlocks = (N + 3) / 4;
    const int w1Tiles = 2 * (D1 / 32) * (F / 32);
    l1_prep_kernel<<<nodeBlocks + w1Tiles, 256, 0, s0>>>(x, N, nodeBlocks, W1l, W1r, F, D1);
    run_mma(Xh, W1, A1h, nullptr, b1, N, D1, 2 * F, 1, s0);

    if (fork) {
        cudaStreamWaitEvent(s0, g_aux.evW, 0);
    } else {
        wconvT_kernel<<<dim3(D2 / 32, D1 / 32), tb, 0, s0>>>(W2l, W2lp, D1, D2);
        wconvT_kernel<<<dim3(D2 / 32, D1 / 32), tb, 0, s0>>>(W2r, W2rp, D1, D2);
        wconvT_kernel<<<dim3(D3 / 32, D2 / 32), tb, 0, s0>>>(W3l, W3lp, D2, D3);
        wconvT_kernel<<<dim3(D3 / 32, D2 / 32), tb, 0, s0>>>(W3r, W3rp, D2, D3);
    }

    // ---- layer 2 ----
    run_mma(A1h, W2lp, P16, nullptr, nullptr, N, D2, D1, 0, s0);
    if (fork) {
        cudaEventRecord(g_aux.evA, s0);
        cudaStreamWaitEvent(g_aux.s2, g_aux.evA, 0);
        gather_sum_h_kernel<<<N, D2 / 8, 0, g_aux.s2>>>(P16, AGGh, D2);
        cudaEventRecord(g_aux.evG, g_aux.s2);
        // GEMM2b half-1, then half-2; add2 half-1 overlaps half-2 on s2
        run_mma(A1h, W2rp, Hpre, nullptr, nullptr, M1, D2, D1, 0, s0);
        cudaEventRecord(g_aux.evH1, s0);
        run_mma(A1h + (long long)M1 * D1, W2rp, Hpre + (long long)M1 * D2,
                nullptr, nullptr, M2, D2, D1, 0, s0);
        cudaStreamWaitEvent(g_aux.s2, g_aux.evH1, 0);    // s2 already past gather2
        {
            const long long tot1 = (long long)M1 * D2;
            add_act_kernel<<<(int)((tot1 / 8 + TPB - 1) / TPB), TPB, 0, g_aux.s2>>>(
                Hpre, AGGh, b2, A2h, tot1, D2);
            cudaEventRecord(g_aux.evD1, g_aux.s2);
        }
        cudaStreamWaitEvent(s0, g_aux.evG, 0);           // AGGh ready for half-2 add
        {
            const long long off = (long long)M1 * D2;
            const long long tot2 = (long long)M2 * D2;
            add_act_kernel<<<(int)((tot2 / 8 + TPB - 1) / TPB), TPB, 0, s0>>>(
                Hpre + off, AGGh + off, b2, A2h + off, tot2, D2);
        }
        cudaStreamWaitEvent(s0, g_aux.evD1, 0);          // half-1 add done
    } else {
        gather_sum_h_kernel<<<N, D2 / 8, 0, s0>>>(P16, AGGh, D2);
        run_mma(A1h, W2rp, Hpre, nullptr, nullptr, N, D2, D1, 0, s0);
        const long long tot = (long long)N * D2;
        add_act_kernel<<<(int)((tot / 8 + TPB - 1) / TPB), TPB, 0, s0>>>(Hpre, AGGh, b2, A2h, tot, D2);
    }

    // ---- layer 3 ----
    run_mma(A2h, W3lp, P16, nullptr, nullptr, N, D3, D2, 0, s0);
    if (fork) {
        cudaEventRecord(g_aux.evA2, s0);
        cudaStreamWaitEvent(g_aux.s2, g_aux.evA2, 0);
        gather_sum_h_kernel<<<N, D3 / 8, 0, g_aux.s2>>>(P16, AGGh, D3);
        cudaEventRecord(g_aux.evG2, g_aux.s2);
        run_mma(A2h, W3rp, Hpre, nullptr, nullptr, M1, D3, D2, 0, s0);
        cudaEventRecord(g_aux.evH1b, s0);
        run_mma(A2h + (long long)M1 * D2, W3rp, Hpre + (long long)M1 * D3,
                nullptr, nullptr, M2, D3, D2, 0, s0);
        cudaStreamWaitEvent(g_aux.s2, g_aux.evH1b, 0);   // s2 already past gather3
        add_act_norm_kernel<<<M1, D3 / 4, 0, g_aux.s2>>>(Hpre, AGGh, b3, out, D3);
        cudaEventRecord(g_aux.evN1, g_aux.s2);
        cudaStreamWaitEvent(s0, g_aux.evG2, 0);
        {
            const long long off = (long long)M1 * D3;
            add_act_norm_kernel<<<M2, D3 / 4, 0, s0>>>(Hpre + off, AGGh + off, b3,
                                                       out + off, D3);
        }
        cudaStreamWaitEvent(s0, g_aux.evN1, 0);          // half-1 norm done
    } else {
        gather_sum_h_kernel<<<N, D3 / 8, 0, s0>>>(P16, AGGh, D3);
        run_mma(A2h, W3rp, Hpre, nullptr, nullptr, N, D3, D2, 0, s0);
        add_act_norm_kernel<<<N, D3 / 4, 0, s0>>>(Hpre, AGGh, b3, out, D3);
    }

    (void)n_in; (void)out_size;
}